// round 1
// baseline (speedup 1.0000x reference)
#include <cuda_runtime.h>
#include <math.h>

// Problem constants
#define Bn 4096
#define Gn 256
#define NCOLS 640      // 128 (pw1) + 128 (dw1) + 128 (nw1) + 256 (cw1)
#define NCHUNK 20      // 640 / 32 column chunks

// Scratch (device globals: allocation-free per harness rules)
__device__ float g_Ptab[NCHUNK * 1024 * 32]; // [chunk][g*4+t][32 cols]  (2.62 MB)
__device__ float g_Hall[Bn * NCOLS];         // per-batch pre-activation hidden (10.5 MB)
__device__ float g_NumConn[Bn];

// ---------------------------------------------------------------------------
// Kernel A: precompute P[g,t,c] = emb[t] . W[g*32:(g+1)*32, c]
// One block per gate g. W columns: [0,128)=pw1, [128,256)=dw1, [256,384)=nw1,
// [384,640)=cw1 (first 8192 rows).
// ---------------------------------------------------------------------------
__global__ void precompute_P(const float* __restrict__ emb,
                             const float* __restrict__ pw1,
                             const float* __restrict__ dw1,
                             const float* __restrict__ nw1,
                             const float* __restrict__ cw1) {
    extern __shared__ float sA[];
    float* Wg   = sA;             // 32 * 640 floats
    float* embS = sA + 32 * 640;  // 4 * 32 floats
    const int g   = blockIdx.x;
    const int tid = threadIdx.x;

    if (tid < 128) embS[tid] = emb[tid];

    for (int k = 0; k < 32; k++) {
        int row = g * 32 + k;
        for (int c = tid; c < 640; c += 256) {
            float v;
            if      (c < 128) v = pw1[row * 128 + c];
            else if (c < 256) v = dw1[row * 128 + (c - 128)];
            else if (c < 384) v = nw1[row * 128 + (c - 256)];
            else              v = cw1[row * 256 + (c - 384)];
            Wg[k * 640 + c] = v;
        }
    }
    __syncthreads();

    for (int idx = tid; idx < 4 * 640; idx += 256) {
        int t = idx / 640;
        int c = idx - t * 640;
        float s = 0.f;
#pragma unroll
        for (int k = 0; k < 32; k++) s += embS[t * 32 + k] * Wg[k * 640 + c];
        int chunk = c >> 5, cc = c & 31;
        g_Ptab[(chunk * 1024 + g * 4 + t) * 32 + cc] = s;
    }
}

// ---------------------------------------------------------------------------
// Kernel B: num_conn[b] = sum over 65536 floats.  Pure HBM stream.
// ---------------------------------------------------------------------------
__global__ void conn_reduce(const float* __restrict__ conn) {
    __shared__ float ws[16];
    const int b = blockIdx.x;
    const float4* p = (const float4*)(conn + (size_t)b * 65536);
    float s = 0.f;
#pragma unroll 4
    for (int i = threadIdx.x; i < 16384; i += 512) {
        float4 v = p[i];
        s += (v.x + v.y) + (v.z + v.w);
    }
#pragma unroll
    for (int o = 16; o; o >>= 1) s += __shfl_xor_sync(0xffffffffu, s, o);
    if ((threadIdx.x & 31) == 0) ws[threadIdx.x >> 5] = s;
    __syncthreads();
    if (threadIdx.x == 0) {
        float t = 0.f;
#pragma unroll
        for (int i = 0; i < 16; i++) t += ws[i];
        g_NumConn[b] = t;
    }
}

// ---------------------------------------------------------------------------
// Kernel C: Hall[b, c] = sum_g P[g, types[b,g], c]
// grid (128 batch-groups of 32, 10 col-groups of 64). 256 threads.
// Thread (b_loc = tid>>3, c4 = tid&7) accumulates 4 cols (float4).
// Lanes 0-7 of a quarter-warp share one batch -> LDS.128 phases conflict-free.
// Types packed 2-bit into 16 regs per thread.
// ---------------------------------------------------------------------------
__global__ void accum_kernel(const int* __restrict__ gate_types) {
    extern __shared__ float sC[];
    float*    tileS  = sC;                         // 1024 * 32 floats (128 KB)
    unsigned* tpackS = (unsigned*)(sC + 32768);    // 32 * 16 words

    const int tid = threadIdx.x;
    const int b0  = blockIdx.x * 32;
    const int cg  = blockIdx.y;

    // pack gate types: 16 gates per u32, 16 words per batch
    for (int i = tid; i < 32 * 16; i += 256) {
        int bl = i >> 4, w = i & 15;
        const int* gt = gate_types + (b0 + bl) * Gn + w * 16;
        unsigned u = 0;
#pragma unroll
        for (int j = 0; j < 16; j++) u |= ((unsigned)gt[j] & 3u) << (2 * j);
        tpackS[i] = u;
    }
    __syncthreads();

    const int bl = tid >> 3;
    const int c4 = tid & 7;
    unsigned tp[16];
#pragma unroll
    for (int w = 0; w < 16; w++) tp[w] = tpackS[bl * 16 + w];

    for (int chunk = 0; chunk < 2; chunk++) {
        const int cbase = cg * 2 + chunk;  // global 32-col chunk id, 0..19
        // cooperative, fully-coalesced 128 KB tile load
        const float4* src = (const float4*)(g_Ptab + (size_t)cbase * 32768);
        float4* dst = (float4*)tileS;
        for (int i = tid; i < 8192; i += 256) dst[i] = src[i];
        __syncthreads();

        float ax = 0.f, ay = 0.f, az = 0.f, aw = 0.f;
        const float4* t4 = (const float4*)tileS;
        for (int w = 0; w < 16; w++) {
            unsigned u = tp[w];
#pragma unroll
            for (int j = 0; j < 16; j++) {
                int t = (int)(u & 3u);
                u >>= 2;
                int g = w * 16 + j;
                float4 v = t4[(g * 4 + t) * 8 + c4];
                ax += v.x; ay += v.y; az += v.z; aw += v.w;
            }
        }
        int b   = b0 + bl;
        int col = cbase * 32 + c4 * 4;
        float4 r; r.x = ax; r.y = ay; r.z = az; r.w = aw;
        *(float4*)(g_Hall + (size_t)b * NCOLS + col) = r;
        __syncthreads();  // before reloading tileS
    }
}

// ---------------------------------------------------------------------------
// Kernel D: heads, entropies, 3-layer correctness MLP.
// 256 blocks x 128 threads; 16 batches per block (amortizes cw2 smem tile).
// ---------------------------------------------------------------------------
__device__ __forceinline__ float softplusf_(float x) {
    return (x > 20.f) ? x : log1pf(expf(x));
}
__device__ __forceinline__ float sigmoidf_(float x) {
    return 1.f / (1.f + expf(-x));
}

__global__ void finalize_kernel(const int* __restrict__ gate_types,
                                const float* __restrict__ inputs,
                                const float* __restrict__ outputs,
                                const float* __restrict__ pb1, const float* __restrict__ pw2, const float* __restrict__ pb2,
                                const float* __restrict__ db1, const float* __restrict__ dw2, const float* __restrict__ db2,
                                const float* __restrict__ nb1, const float* __restrict__ nw2, const float* __restrict__ nb2,
                                const float* __restrict__ cw1, const float* __restrict__ cb1,
                                const float* __restrict__ cw2, const float* __restrict__ cb2,
                                const float* __restrict__ cw3, const float* __restrict__ cb3,
                                float* __restrict__ out) {
    extern __shared__ float sD[];
    float* h1s  = sD;             // 16 * 256
    float* cw2t = sD + 4096;      // 64 * 128
    float* redA = sD + 12288;     // 4 * 8
    float* red2 = sD + 12320;     // 16 * 4

    const int tid  = threadIdx.x;
    const int lane = tid & 31, warp = tid >> 5;
    const int gb   = blockIdx.x * 16;

    const float pb1j = pb1[tid], db1j = db1[tid], nb1j = nb1[tid];
    const float pw2j = pw2[tid], dw2j = dw2[tid], nw2j = nw2[tid];
    const float cb1a = cb1[tid], cb1b = cb1[tid + 128];
    float win_a[12], win_b[12];
#pragma unroll
    for (int i = 0; i < 12; i++) {
        win_a[i] = cw1[(8192 + i) * 256 + tid];
        win_b[i] = cw1[(8192 + i) * 256 + tid + 128];
    }

    for (int bl = 0; bl < 16; bl++) {
        const int b = gb + bl;
        const float* H = g_Hall + (size_t)b * NCOLS;
        float hp = fmaxf(H[tid]       + pb1j, 0.f);
        float hd = fmaxf(H[128 + tid] + db1j, 0.f);
        float hn = fmaxf(H[256 + tid] + nb1j, 0.f);
        float vp = hp * pw2j, vd = hd * dw2j, vn = hn * nw2j;

        int t0 = gate_types[b * 256 + 2 * tid];
        int t1 = gate_types[b * 256 + 2 * tid + 1];
        float c0 = (float)((t0 == 0) + (t1 == 0));
        float c1 = (float)((t0 == 1) + (t1 == 1));
        float c2 = (float)((t0 == 2) + (t1 == 2));
        float c3 = (float)((t0 == 3) + (t1 == 3));

        float ha = H[384 + tid] + cb1a;
        float hb = H[512 + tid] + cb1b;
#pragma unroll
        for (int i = 0; i < 8; i++) {
            float x = inputs[b * 8 + i];
            ha += x * win_a[i]; hb += x * win_b[i];
        }
#pragma unroll
        for (int i = 0; i < 4; i++) {
            float x = outputs[b * 4 + i];
            ha += x * win_a[8 + i]; hb += x * win_b[8 + i];
        }
        h1s[bl * 256 + tid]       = fmaxf(ha, 0.f);
        h1s[bl * 256 + 128 + tid] = fmaxf(hb, 0.f);

#pragma unroll
        for (int o = 16; o; o >>= 1) {
            vp += __shfl_xor_sync(0xffffffffu, vp, o);
            vd += __shfl_xor_sync(0xffffffffu, vd, o);
            vn += __shfl_xor_sync(0xffffffffu, vn, o);
            c0 += __shfl_xor_sync(0xffffffffu, c0, o);
            c1 += __shfl_xor_sync(0xffffffffu, c1, o);
            c2 += __shfl_xor_sync(0xffffffffu, c2, o);
            c3 += __shfl_xor_sync(0xffffffffu, c3, o);
        }
        if (lane == 0) {
            float* r = redA + warp * 8;
            r[0] = vp; r[1] = vd; r[2] = vn;
            r[3] = c0; r[4] = c1; r[5] = c2; r[6] = c3;
        }
        __syncthreads();
        if (tid == 0) {
            float sp = 0, sd = 0, sn = 0, k0 = 0, k1 = 0, k2 = 0, k3 = 0;
#pragma unroll
            for (int w = 0; w < 4; w++) {
                float* r = redA + w * 8;
                sp += r[0]; sd += r[1]; sn += r[2];
                k0 += r[3]; k1 += r[4]; k2 += r[5]; k3 += r[6];
            }
            float nc = g_NumConn[b];
            float energy = softplusf_(sp + pb2[0]) + 0.05f * nc;  // 0.5 * 0.1
            float delay  = softplusf_(sd + db2[0]);
            float stab   = sigmoidf_(sn + nb2[0]) * expf(-1.f);
            float ent = 0.f;
            float ks[4] = {k0, k1, k2, k3};
#pragma unroll
            for (int i = 0; i < 4; i++) {
                float p = ks[i] * (1.f / 256.f);
                if (p > 0.f) ent -= p * log2f(p);
            }
            float dens = nc * (1.f / 65536.f);
            if (dens > 0.f && dens < 1.f) {
                float d = fminf(fmaxf(dens, 1e-12f), 1.f - 1e-12f);
                ent += -d * log2f(d) - (1.f - d) * log2f(1.f - d);
            }
            out[b]            = energy;
            out[4096 + b]     = ent;
            out[2 * 4096 + b] = stab;
            out[4 * 4096 + b] = delay;
        }
        __syncthreads();
    }

    // correctness second + third layer
    float acc[16];
#pragma unroll
    for (int i = 0; i < 16; i++) acc[i] = 0.f;
    for (int jc = 0; jc < 4; jc++) {
        const float4* src = (const float4*)(cw2 + jc * 64 * 128);
        float4* dst = (float4*)cw2t;
        for (int i = tid; i < 2048; i += 128) dst[i] = src[i];
        __syncthreads();
#pragma unroll
        for (int bl = 0; bl < 16; bl++) {
            float a = acc[bl];
            const float* h1p = h1s + bl * 256 + jc * 64;
#pragma unroll 8
            for (int jj = 0; jj < 64; jj++)
                a += h1p[jj] * cw2t[jj * 128 + tid];
            acc[bl] = a;
        }
        __syncthreads();
    }
    const float cb2j = cb2[tid], w3 = cw3[tid];
#pragma unroll
    for (int bl = 0; bl < 16; bl++) {
        float h2 = fmaxf(acc[bl] + cb2j, 0.f);
        float v  = h2 * w3;
#pragma unroll
        for (int o = 16; o; o >>= 1) v += __shfl_xor_sync(0xffffffffu, v, o);
        if (lane == 0) red2[bl * 4 + warp] = v;
    }
    __syncthreads();
    if (tid < 16) {
        float s = red2[tid * 4] + red2[tid * 4 + 1] + red2[tid * 4 + 2] + red2[tid * 4 + 3];
        out[3 * 4096 + gb + tid] = sigmoidf_(s + cb3[0]);
    }
}

// ---------------------------------------------------------------------------
extern "C" void kernel_launch(void* const* d_in, const int* in_sizes, int n_in,
                              void* d_out, int out_size) {
    (void)in_sizes; (void)n_in; (void)out_size;
    const int*   gate_types  = (const int*)  d_in[0];
    const float* connections = (const float*)d_in[1];
    const float* inputs      = (const float*)d_in[2];
    const float* outputs     = (const float*)d_in[3];
    const float* emb         = (const float*)d_in[4];
    const float* pw1 = (const float*)d_in[5];
    const float* pb1 = (const float*)d_in[6];
    const float* pw2 = (const float*)d_in[7];
    const float* pb2 = (const float*)d_in[8];
    const float* dw1 = (const float*)d_in[9];
    const float* db1 = (const float*)d_in[10];
    const float* dw2 = (const float*)d_in[11];
    const float* db2 = (const float*)d_in[12];
    const float* nw1 = (const float*)d_in[13];
    const float* nb1 = (const float*)d_in[14];
    const float* nw2 = (const float*)d_in[15];
    const float* nb2 = (const float*)d_in[16];
    const float* cw1 = (const float*)d_in[17];
    const float* cb1 = (const float*)d_in[18];
    const float* cw2 = (const float*)d_in[19];
    const float* cb2 = (const float*)d_in[20];
    const float* cw3 = (const float*)d_in[21];
    const float* cb3 = (const float*)d_in[22];
    float* out = (float*)d_out;

    const int smemA = 32 * 640 * 4 + 128 * 4;       // 82432 B
    const int smemC = 32768 * 4 + 512 * 4;          // 133120 B
    const int smemD = 12384 * 4;                    // 49536 B
    cudaFuncSetAttribute(precompute_P,   cudaFuncAttributeMaxDynamicSharedMemorySize, smemA);
    cudaFuncSetAttribute(accum_kernel,   cudaFuncAttributeMaxDynamicSharedMemorySize, smemC);
    cudaFuncSetAttribute(finalize_kernel,cudaFuncAttributeMaxDynamicSharedMemorySize, smemD);

    precompute_P<<<256, 256, smemA>>>(emb, pw1, dw1, nw1, cw1);
    conn_reduce<<<4096, 512>>>(connections);
    accum_kernel<<<dim3(128, 10), 256, smemC>>>(gate_types);
    finalize_kernel<<<256, 128, smemD>>>(gate_types, inputs, outputs,
                                         pb1, pw2, pb2, db1, dw2, db2,
                                         nb1, nw2, nb2, cw1, cb1,
                                         cw2, cb2, cw3, cb3, out);
}

// round 2
// speedup vs baseline: 1.2175x; 1.2175x over previous
#include <cuda_runtime.h>
#include <math.h>

// Problem constants
#define Bn 4096
#define Gn 256
#define NCOLS 640      // 128 (pw1) + 128 (dw1) + 128 (nw1) + 256 (cw1)
#define NCHUNK 20      // 640 / 32 column chunks

// Scratch (device globals: allocation-free per harness rules)
__device__ float g_Ptab[NCHUNK * 1024 * 32]; // [chunk][g*4+t][32 cols]  (2.62 MB)
__device__ float g_Hall[Bn * NCOLS];         // per-batch pre-activation hidden (10.5 MB)
__device__ float g_NumConn[Bn];

// ---------------------------------------------------------------------------
// Kernel A: precompute P[g,t,c] = emb[t] . W[g*32:(g+1)*32, c]
// ---------------------------------------------------------------------------
__global__ void precompute_P(const float* __restrict__ emb,
                             const float* __restrict__ pw1,
                             const float* __restrict__ dw1,
                             const float* __restrict__ nw1,
                             const float* __restrict__ cw1) {
    extern __shared__ float sA[];
    float* Wg   = sA;             // 32 * 640 floats
    float* embS = sA + 32 * 640;  // 4 * 32 floats
    const int g   = blockIdx.x;
    const int tid = threadIdx.x;

    if (tid < 128) embS[tid] = emb[tid];

    for (int k = 0; k < 32; k++) {
        int row = g * 32 + k;
        for (int c = tid; c < 640; c += 256) {
            float v;
            if      (c < 128) v = pw1[row * 128 + c];
            else if (c < 256) v = dw1[row * 128 + (c - 128)];
            else if (c < 384) v = nw1[row * 128 + (c - 256)];
            else              v = cw1[row * 256 + (c - 384)];
            Wg[k * 640 + c] = v;
        }
    }
    __syncthreads();

    for (int idx = tid; idx < 4 * 640; idx += 256) {
        int t = idx / 640;
        int c = idx - t * 640;
        float s = 0.f;
#pragma unroll
        for (int k = 0; k < 32; k++) s += embS[t * 32 + k] * Wg[k * 640 + c];
        int chunk = c >> 5, cc = c & 31;
        g_Ptab[(chunk * 1024 + g * 4 + t) * 32 + cc] = s;
    }
}

// ---------------------------------------------------------------------------
// Fused main kernel: role-split blocks overlap the HBM-bound connections
// reduction with the smem-crossbar-bound gather-accumulate.
// Grid: 4736 blocks = 64 groups of 74 (10 accum + 64 conn). 512 threads.
// ---------------------------------------------------------------------------
__global__ void fused_main(const float* __restrict__ conn,
                           const int* __restrict__ gate_types) {
    extern __shared__ float sC[];
    const int tid = threadIdx.x;
    const int grp = blockIdx.x / 74;
    const int r   = blockIdx.x % 74;

    if (r >= 10) {
        // ---------------- connections reduction role ----------------
        const int b = grp * 64 + (r - 10);
        const float4* p = (const float4*)(conn + (size_t)b * 65536);
        float s = 0.f;
        // 16384 float4 / 512 threads = 32 per thread, 8-way MLP batches
        for (int base = 0; base < 16384; base += 4096) {
            float4 v0 = p[base + tid];
            float4 v1 = p[base + tid + 512];
            float4 v2 = p[base + tid + 1024];
            float4 v3 = p[base + tid + 1536];
            float4 v4 = p[base + tid + 2048];
            float4 v5 = p[base + tid + 2560];
            float4 v6 = p[base + tid + 3072];
            float4 v7 = p[base + tid + 3584];
            s += ((v0.x + v0.y) + (v0.z + v0.w)) + ((v1.x + v1.y) + (v1.z + v1.w));
            s += ((v2.x + v2.y) + (v2.z + v2.w)) + ((v3.x + v3.y) + (v3.z + v3.w));
            s += ((v4.x + v4.y) + (v4.z + v4.w)) + ((v5.x + v5.y) + (v5.z + v5.w));
            s += ((v6.x + v6.y) + (v6.z + v6.w)) + ((v7.x + v7.y) + (v7.z + v7.w));
        }
#pragma unroll
        for (int o = 16; o; o >>= 1) s += __shfl_xor_sync(0xffffffffu, s, o);
        float* ws = sC;
        if ((tid & 31) == 0) ws[tid >> 5] = s;
        __syncthreads();
        if (tid == 0) {
            float t = 0.f;
#pragma unroll
            for (int i = 0; i < 16; i++) t += ws[i];
            g_NumConn[b] = t;
        }
        return;
    }

    // ---------------- accumulate role ----------------
    // Hall[b, c] = sum_g P[g, types[b,g], c].  64 batches, 2 col-chunks.
    float*    tileS  = sC;                       // 32768 floats (128 KB)
    unsigned* tpackS = (unsigned*)(sC + 32768);  // 1024 words

    const int b0 = grp * 64;
    const int cg = r;  // 0..9

    // pack gate types: 16 gates (2 bits each) per u32, 16 words per batch
    for (int i = tid; i < 64 * 16; i += 512) {
        int bl = i >> 4, w = i & 15;
        const int4* gt = (const int4*)(gate_types + (b0 + bl) * Gn + w * 16);
        int4 a = gt[0], b4 = gt[1], c = gt[2], d = gt[3];
        unsigned u = 0;
        u |= ((unsigned)a.x & 3u);        u |= ((unsigned)a.y & 3u) << 2;
        u |= ((unsigned)a.z & 3u) << 4;   u |= ((unsigned)a.w & 3u) << 6;
        u |= ((unsigned)b4.x & 3u) << 8;  u |= ((unsigned)b4.y & 3u) << 10;
        u |= ((unsigned)b4.z & 3u) << 12; u |= ((unsigned)b4.w & 3u) << 14;
        u |= ((unsigned)c.x & 3u) << 16;  u |= ((unsigned)c.y & 3u) << 18;
        u |= ((unsigned)c.z & 3u) << 20;  u |= ((unsigned)c.w & 3u) << 22;
        u |= ((unsigned)d.x & 3u) << 24;  u |= ((unsigned)d.y & 3u) << 26;
        u |= ((unsigned)d.z & 3u) << 28;  u |= ((unsigned)d.w & 3u) << 30;
        tpackS[i] = u;
    }
    __syncthreads();

    const int bl = tid >> 3;   // 0..63
    const int c4 = tid & 7;    // 0..7
    unsigned tp[16];
#pragma unroll
    for (int w = 0; w < 16; w++) tp[w] = tpackS[bl * 16 + w];

    for (int chunk = 0; chunk < 2; chunk++) {
        const int cbase = cg * 2 + chunk;  // global 32-col chunk, 0..19
        const float4* src = (const float4*)(g_Ptab + (size_t)cbase * 32768);
        float4* dst = (float4*)tileS;
        for (int i = tid; i < 8192; i += 512) dst[i] = src[i];
        __syncthreads();

        float ax = 0.f, ay = 0.f, az = 0.f, aw = 0.f;
        const float4* t4 = (const float4*)tileS;
        for (int w = 0; w < 16; w++) {
            unsigned u = tp[w];
#pragma unroll
            for (int j = 0; j < 16; j++) {
                int t = (int)(u & 3u);
                u >>= 2;
                int g = w * 16 + j;
                float4 v = t4[(g * 4 + t) * 8 + c4];
                ax += v.x; ay += v.y; az += v.z; aw += v.w;
            }
        }
        int b   = b0 + bl;
        int col = cbase * 32 + c4 * 4;
        float4 rr; rr.x = ax; rr.y = ay; rr.z = az; rr.w = aw;
        *(float4*)(g_Hall + (size_t)b * NCOLS + col) = rr;
        __syncthreads();
    }
}

// ---------------------------------------------------------------------------
// Finalize: heads, entropies, 3-layer correctness MLP.
// 256 blocks x 256 threads; 16 batches per block.
// ---------------------------------------------------------------------------
__device__ __forceinline__ float softplusf_(float x) {
    return (x > 20.f) ? x : log1pf(expf(x));
}
__device__ __forceinline__ float sigmoidf_(float x) {
    return 1.f / (1.f + expf(-x));
}

// smem layout (floats)
#define F_H1S   0        // 4096
#define F_CW2T  4096     // 8192
#define F_BIAS  12288    // 768  (pb1|db1|nb1|pw2|dw2|nw2, 128 each)
#define F_CB1   13056    // 256
#define F_WIN   13312    // 3072 (win[i][c] = cw1[(8192+i)*256+c])
#define F_REDA  16384    // 128  (16 batches x 8)
#define F_PACC  16512    // 2048 (16 x 128)
#define F_RED2  18560    // 64
#define F_TOT   18624

__global__ void finalize_kernel(const int* __restrict__ gate_types,
                                const float* __restrict__ inputs,
                                const float* __restrict__ outputs,
                                const float* __restrict__ pb1, const float* __restrict__ pw2, const float* __restrict__ pb2,
                                const float* __restrict__ db1, const float* __restrict__ dw2, const float* __restrict__ db2,
                                const float* __restrict__ nb1, const float* __restrict__ nw2, const float* __restrict__ nb2,
                                const float* __restrict__ cw1, const float* __restrict__ cb1,
                                const float* __restrict__ cw2, const float* __restrict__ cb2,
                                const float* __restrict__ cw3, const float* __restrict__ cb3,
                                float* __restrict__ out) {
    extern __shared__ float sD[];
    float* h1s   = sD + F_H1S;
    float* cw2t  = sD + F_CW2T;
    float* biasS = sD + F_BIAS;
    float* cb1S  = sD + F_CB1;
    float* winS  = sD + F_WIN;
    float* redA  = sD + F_REDA;
    float* pacc  = sD + F_PACC;
    float* red2  = sD + F_RED2;

    const int tid  = threadIdx.x;
    const int lane = tid & 31, warp = tid >> 5;
    const int gb   = blockIdx.x * 16;

    // ---- preload weights/biases ----
    if (tid < 128) {
        biasS[tid]       = pb1[tid];
        biasS[128 + tid] = db1[tid];
        biasS[256 + tid] = nb1[tid];
        biasS[384 + tid] = pw2[tid];
        biasS[512 + tid] = dw2[tid];
        biasS[640 + tid] = nw2[tid];
    }
    cb1S[tid] = cb1[tid];
    const float* winsrc = cw1 + 8192 * 256;
    for (int i = tid; i < 3072; i += 256) winS[i] = winsrc[i];
    __syncthreads();

    // ---- phase 1: heads + type counts + correctness layer 1 ----
    // 8 warps, 2 batches each, no block syncs inside
    for (int q = 0; q < 2; q++) {
        const int bl = warp * 2 + q;
        const int b  = gb + bl;
        const float* H = g_Hall + (size_t)b * NCOLS;

        float vp = 0.f, vd = 0.f, vn = 0.f;
#pragma unroll
        for (int k = 0; k < 4; k++) {
            int c = lane + 32 * k;
            float hp = fmaxf(H[c]       + biasS[c],       0.f);
            float hd = fmaxf(H[128 + c] + biasS[128 + c], 0.f);
            float hn = fmaxf(H[256 + c] + biasS[256 + c], 0.f);
            vp += hp * biasS[384 + c];
            vd += hd * biasS[512 + c];
            vn += hn * biasS[640 + c];
        }

        // type counts: 8 ints per lane
        const int4* tq = (const int4*)(gate_types + (size_t)b * Gn);
        int4 ta = tq[lane * 2], tb = tq[lane * 2 + 1];
        float c0, c1, c2, c3;
        {
            int k0 = (ta.x == 0) + (ta.y == 0) + (ta.z == 0) + (ta.w == 0)
                   + (tb.x == 0) + (tb.y == 0) + (tb.z == 0) + (tb.w == 0);
            int k1 = (ta.x == 1) + (ta.y == 1) + (ta.z == 1) + (ta.w == 1)
                   + (tb.x == 1) + (tb.y == 1) + (tb.z == 1) + (tb.w == 1);
            int k2 = (ta.x == 2) + (ta.y == 2) + (ta.z == 2) + (ta.w == 2)
                   + (tb.x == 2) + (tb.y == 2) + (tb.z == 2) + (tb.w == 2);
            int k3 = (ta.x == 3) + (ta.y == 3) + (ta.z == 3) + (ta.w == 3)
                   + (tb.x == 3) + (tb.y == 3) + (tb.z == 3) + (tb.w == 3);
            c0 = (float)k0; c1 = (float)k1; c2 = (float)k2; c3 = (float)k3;
        }

        // inputs/outputs broadcast value
        float xv = 0.f;
        if (lane < 8)        xv = inputs[b * 8 + lane];
        else if (lane < 12)  xv = outputs[b * 4 + lane - 8];

        // correctness layer 1 (256 wide, 8 per lane)
#pragma unroll
        for (int k = 0; k < 8; k++) {
            int c2i = lane + 32 * k;
            float ha = H[384 + c2i] + cb1S[c2i];
#pragma unroll
            for (int i = 0; i < 12; i++) {
                float x = __shfl_sync(0xffffffffu, xv, i);
                ha += x * winS[i * 256 + c2i];
            }
            h1s[bl * 256 + c2i] = fmaxf(ha, 0.f);
        }

#pragma unroll
        for (int o = 16; o; o >>= 1) {
            vp += __shfl_xor_sync(0xffffffffu, vp, o);
            vd += __shfl_xor_sync(0xffffffffu, vd, o);
            vn += __shfl_xor_sync(0xffffffffu, vn, o);
            c0 += __shfl_xor_sync(0xffffffffu, c0, o);
            c1 += __shfl_xor_sync(0xffffffffu, c1, o);
            c2 += __shfl_xor_sync(0xffffffffu, c2, o);
            c3 += __shfl_xor_sync(0xffffffffu, c3, o);
        }
        if (lane == 0) {
            float* rr = redA + bl * 8;
            rr[0] = vp; rr[1] = vd; rr[2] = vn;
            rr[3] = c0; rr[4] = c1; rr[5] = c2; rr[6] = c3;
        }
    }
    __syncthreads();

    // parallel per-batch scalar finalization (16 threads)
    if (tid < 16) {
        const int b = gb + tid;
        float* rr = redA + tid * 8;
        float nc = g_NumConn[b];
        float energy = softplusf_(rr[0] + pb2[0]) + 0.05f * nc;
        float delay  = softplusf_(rr[1] + db2[0]);
        float stab   = sigmoidf_(rr[2] + nb2[0]) * 0.36787944117144233f;
        float ent = 0.f;
#pragma unroll
        for (int i = 0; i < 4; i++) {
            float p = rr[3 + i] * (1.f / 256.f);
            if (p > 0.f) ent -= p * log2f(p);
        }
        float dens = nc * (1.f / 65536.f);
        if (dens > 0.f && dens < 1.f) {
            float d = fminf(fmaxf(dens, 1e-12f), 1.f - 1e-12f);
            ent += -d * log2f(d) - (1.f - d) * log2f(1.f - d);
        }
        out[b]            = energy;
        out[4096 + b]     = ent;
        out[2 * 4096 + b] = stab;
        out[4 * 4096 + b] = delay;
    }

    // ---- phase 2: correctness layers 2+3 ----
    // 256 threads: col = tid&127, sub = tid>>7 handles half the rows of each tile
    const int col = tid & 127;
    const int sub = tid >> 7;
    float acc[16];
#pragma unroll
    for (int i = 0; i < 16; i++) acc[i] = 0.f;

    for (int jc = 0; jc < 4; jc++) {
        __syncthreads();  // previous tile fully consumed
        const float4* src = (const float4*)(cw2 + jc * 64 * 128);
        float4* dst = (float4*)cw2t;
        for (int i = tid; i < 2048; i += 256) dst[i] = src[i];
        __syncthreads();

        const int jbase = sub * 32;
#pragma unroll
        for (int jj0 = 0; jj0 < 32; jj0 += 4) {
            float w0 = cw2t[(jbase + jj0 + 0) * 128 + col];
            float w1 = cw2t[(jbase + jj0 + 1) * 128 + col];
            float w2v = cw2t[(jbase + jj0 + 2) * 128 + col];
            float w3v = cw2t[(jbase + jj0 + 3) * 128 + col];
#pragma unroll
            for (int bl = 0; bl < 16; bl++) {
                float4 h = *(const float4*)&h1s[bl * 256 + jc * 64 + jbase + jj0];
                acc[bl] += h.x * w0 + h.y * w1 + h.z * w2v + h.w * w3v;
            }
        }
    }
    __syncthreads();
    if (sub == 1) {
#pragma unroll
        for (int bl = 0; bl < 16; bl++) pacc[bl * 128 + col] = acc[bl];
    }
    __syncthreads();
    if (sub == 0) {
        const float cb2j = cb2[col], w3 = cw3[col];
#pragma unroll
        for (int bl = 0; bl < 16; bl++) {
            float a = acc[bl] + pacc[bl * 128 + col];
            float h2 = fmaxf(a + cb2j, 0.f);
            float v  = h2 * w3;
#pragma unroll
            for (int o = 16; o; o >>= 1) v += __shfl_xor_sync(0xffffffffu, v, o);
            if (lane == 0) red2[bl * 4 + warp] = v;
        }
    }
    __syncthreads();
    if (tid < 16) {
        float s = red2[tid * 4] + red2[tid * 4 + 1] + red2[tid * 4 + 2] + red2[tid * 4 + 3];
        out[3 * 4096 + gb + tid] = sigmoidf_(s + cb3[0]);
    }
}

// ---------------------------------------------------------------------------
extern "C" void kernel_launch(void* const* d_in, const int* in_sizes, int n_in,
                              void* d_out, int out_size) {
    (void)in_sizes; (void)n_in; (void)out_size;
    const int*   gate_types  = (const int*)  d_in[0];
    const float* connections = (const float*)d_in[1];
    const float* inputs      = (const float*)d_in[2];
    const float* outputs     = (const float*)d_in[3];
    const float* emb         = (const float*)d_in[4];
    const float* pw1 = (const float*)d_in[5];
    const float* pb1 = (const float*)d_in[6];
    const float* pw2 = (const float*)d_in[7];
    const float* pb2 = (const float*)d_in[8];
    const float* dw1 = (const float*)d_in[9];
    const float* db1 = (const float*)d_in[10];
    const float* dw2 = (const float*)d_in[11];
    const float* db2 = (const float*)d_in[12];
    const float* nw1 = (const float*)d_in[13];
    const float* nb1 = (const float*)d_in[14];
    const float* nw2 = (const float*)d_in[15];
    const float* nb2 = (const float*)d_in[16];
    const float* cw1 = (const float*)d_in[17];
    const float* cb1 = (const float*)d_in[18];
    const float* cw2 = (const float*)d_in[19];
    const float* cb2 = (const float*)d_in[20];
    const float* cw3 = (const float*)d_in[21];
    const float* cb3 = (const float*)d_in[22];
    float* out = (float*)d_out;

    const int smemA = 32 * 640 * 4 + 128 * 4;       // 82432 B
    const int smemF = 32768 * 4 + 1024 * 4;         // 135168 B
    const int smemD = F_TOT * 4;                    // 74496 B
    cudaFuncSetAttribute(precompute_P,   cudaFuncAttributeMaxDynamicSharedMemorySize, smemA);
    cudaFuncSetAttribute(fused_main,     cudaFuncAttributeMaxDynamicSharedMemorySize, smemF);
    cudaFuncSetAttribute(finalize_kernel,cudaFuncAttributeMaxDynamicSharedMemorySize, smemD);

    precompute_P<<<256, 256, smemA>>>(emb, pw1, dw1, nw1, cw1);
    fused_main<<<4736, 512, smemF>>>(connections, gate_types);
    finalize_kernel<<<256, 256, smemD>>>(gate_types, inputs, outputs,
                                         pb1, pw2, pb2, db1, dw2, db2,
                                         nb1, nw2, nb2, cw1, cb1,
                                         cw2, cb2, cw3, cb3, out);
}

// round 3
// speedup vs baseline: 1.9449x; 1.5975x over previous
#include <cuda_runtime.h>
#include <math.h>

// Problem constants
#define Bn 4096
#define Gn 256
#define NCOLS 640      // 128 (pw1) + 128 (dw1) + 128 (nw1) + 256 (cw1)

// Scratch (device globals: allocation-free per harness rules)
__device__ float g_Ptab[1024 * 640];           // [g*4+t][c]              2.62 MB
__device__ float g_P2tab[20 * 128 * 16 * 32];  // [chunk][pair][combo][c] 5.24 MB
__device__ float g_Hall[Bn * NCOLS];           // pre-activation hidden  10.5 MB
__device__ float g_NumConn[Bn];

// ---------------------------------------------------------------------------
// Kernel A: P[g,t,c] = emb[t] . W[g*32:(g+1)*32, c]   (direct, no smem stage)
// grid 256 (gate), block 640 (col). 32 independent coalesced loads/thread.
// ---------------------------------------------------------------------------
__global__ __launch_bounds__(640) void precompute_P(
        const float* __restrict__ emb,
        const float* __restrict__ pw1, const float* __restrict__ dw1,
        const float* __restrict__ nw1, const float* __restrict__ cw1) {
    __shared__ float embS[128];
    const int g = blockIdx.x, c = threadIdx.x;
    if (c < 128) embS[c] = emb[c];
    __syncthreads();

    const float* src; int stride;
    if      (c < 128) { src = pw1 + c;         stride = 128; }
    else if (c < 256) { src = dw1 + (c - 128); stride = 128; }
    else if (c < 384) { src = nw1 + (c - 256); stride = 128; }
    else              { src = cw1 + (c - 384); stride = 256; }
    src += (size_t)g * 32 * stride;

    float a0 = 0.f, a1 = 0.f, a2 = 0.f, a3 = 0.f;
#pragma unroll
    for (int k = 0; k < 32; k += 4) {
        float w0 = src[(k + 0) * stride];
        float w1 = src[(k + 1) * stride];
        float w2 = src[(k + 2) * stride];
        float w3 = src[(k + 3) * stride];
        a0 += embS[k] * w0 + embS[k+1] * w1 + embS[k+2] * w2 + embS[k+3] * w3;
        a1 += embS[32+k] * w0 + embS[33+k] * w1 + embS[34+k] * w2 + embS[35+k] * w3;
        a2 += embS[64+k] * w0 + embS[65+k] * w1 + embS[66+k] * w2 + embS[67+k] * w3;
        a3 += embS[96+k] * w0 + embS[97+k] * w1 + embS[98+k] * w2 + embS[99+k] * w3;
    }
    g_Ptab[(g * 4 + 0) * 640 + c] = a0;
    g_Ptab[(g * 4 + 1) * 640 + c] = a1;
    g_Ptab[(g * 4 + 2) * 640 + c] = a2;
    g_Ptab[(g * 4 + 3) * 640 + c] = a3;
}

// ---------------------------------------------------------------------------
// Kernel B: pair table P2[pair, t1*4+t2, c] = P[2p,t1,c] + P[2p+1,t2,c]
// grid 128 (pair), block 640 (col).
// ---------------------------------------------------------------------------
__global__ __launch_bounds__(640) void build_P2() {
    const int p = blockIdx.x, c = threadIdx.x;
    float a[4], b[4];
#pragma unroll
    for (int t = 0; t < 4; t++) {
        a[t] = g_Ptab[((2 * p) * 4 + t) * 640 + c];
        b[t] = g_Ptab[((2 * p + 1) * 4 + t) * 640 + c];
    }
    const int ch = c >> 5, cc = c & 31;
    float* base = g_P2tab + ((size_t)(ch * 128 + p) * 16) * 32 + cc;
#pragma unroll
    for (int t1 = 0; t1 < 4; t1++)
#pragma unroll
        for (int t2 = 0; t2 < 4; t2++)
            base[(t1 * 4 + t2) * 32] = a[t1] + b[t2];
}

// ---------------------------------------------------------------------------
// Fused main: instruction-level interleave of
//   (a) Hall[b,c] = sum_pair P2[pair, combo(b,pair), c]    (smem-crossbar)
//   (b) num_conn rows                                       (HBM stream)
// grid 640 = 64 batch-groups x 10 col-groups; blocks with cg<8 own 8 conn rows.
// 8 subtiles (2 chunks x 4 pair-blocks); 1 conn row interleaved per subtile.
// ---------------------------------------------------------------------------
__global__ __launch_bounds__(512, 2) void fused_main(
        const float* __restrict__ conn, const int* __restrict__ gate_types) {
    extern __shared__ float sC[];
    float*    tileS  = sC;                       // 16384 floats (64 KB)
    unsigned* tpackS = (unsigned*)(sC + 16384);  // 1024 words (combos)
    float*    ws     = sC + 16384 + 1024;        // 16 floats

    const int tid = threadIdx.x;
    const int grp = blockIdx.x / 10;
    const int cg  = blockIdx.x % 10;
    const int b0  = grp * 64;
    const bool doConn = (cg < 8);

    // pack combos: 8 pairs (4 bits each) per u32, 16 words per batch
    for (int i = tid; i < 1024; i += 512) {
        int blc = i >> 4, w = i & 15;
        const int4* gt = (const int4*)(gate_types + (size_t)(b0 + blc) * Gn + w * 16);
        int4 A = gt[0], B4 = gt[1], C = gt[2], D = gt[3];
        unsigned u = 0;
        u |= (unsigned)(A.x * 4 + A.y);
        u |= (unsigned)(A.z * 4 + A.w) << 4;
        u |= (unsigned)(B4.x * 4 + B4.y) << 8;
        u |= (unsigned)(B4.z * 4 + B4.w) << 12;
        u |= (unsigned)(C.x * 4 + C.y) << 16;
        u |= (unsigned)(C.z * 4 + C.w) << 20;
        u |= (unsigned)(D.x * 4 + D.y) << 24;
        u |= (unsigned)(D.z * 4 + D.w) << 28;
        tpackS[i] = u;
    }
    __syncthreads();

    const int bl = tid >> 3;   // local batch 0..63
    const int c4 = tid & 7;    // float4 col slot 0..7

    float ax = 0.f, ay = 0.f, az = 0.f, aw = 0.f;

#pragma unroll
    for (int s = 0; s < 8; s++) {
        const int chalf = s >> 2;          // which 32-col chunk of this cg
        const int pb    = s & 3;           // pair-block (32 pairs)
        const int chunk = cg * 2 + chalf;

        // load 64 KB subtile [32 pairs][16 combos][32 cols]
        {
            const float4* srcT = (const float4*)(g_P2tab +
                                 ((size_t)(chunk * 128 + pb * 32) * 16) * 32);
            float4* dstT = (float4*)tileS;
            for (int i = tid; i < 4096; i += 512) dstT[i] = srcT[i];
        }
        __syncthreads();

        const int row = b0 + ((cg < 8) ? cg : 0) * 8 + s;
        const float4* cp4 = (const float4*)conn + ((size_t)row << 14) + tid;
        float rsum = 0.f;

#pragma unroll
        for (int half = 0; half < 4; half++) {
            const unsigned word = tpackS[bl * 16 + pb * 4 + half];

            // --- sub-batch 1: issue 4 HBM loads, hide under 4 pair-iters ---
            float4 q0, q1, q2, q3;
            if (doConn) {
                q0 = cp4[(half * 8 + 0) * 512];
                q1 = cp4[(half * 8 + 1) * 512];
                q2 = cp4[(half * 8 + 2) * 512];
                q3 = cp4[(half * 8 + 3) * 512];
            } else {
                q0 = q1 = q2 = q3 = make_float4(0.f, 0.f, 0.f, 0.f);
            }
#pragma unroll
            for (int i = 0; i < 4; i++) {
                int combo = (int)((word >> (i * 4)) & 15u);
                const float4 v = *(const float4*)&tileS[((half * 8 + i) * 16 + combo) * 32 + c4 * 4];
                ax += v.x; ay += v.y; az += v.z; aw += v.w;
            }
            rsum += (((q0.x + q0.y) + (q0.z + q0.w)) + ((q1.x + q1.y) + (q1.z + q1.w)))
                  + (((q2.x + q2.y) + (q2.z + q2.w)) + ((q3.x + q3.y) + (q3.z + q3.w)));

            // --- sub-batch 2 ---
            if (doConn) {
                q0 = cp4[(half * 8 + 4) * 512];
                q1 = cp4[(half * 8 + 5) * 512];
                q2 = cp4[(half * 8 + 6) * 512];
                q3 = cp4[(half * 8 + 7) * 512];
            } else {
                q0 = q1 = q2 = q3 = make_float4(0.f, 0.f, 0.f, 0.f);
            }
#pragma unroll
            for (int i = 4; i < 8; i++) {
                int combo = (int)((word >> (i * 4)) & 15u);
                const float4 v = *(const float4*)&tileS[((half * 8 + i) * 16 + combo) * 32 + c4 * 4];
                ax += v.x; ay += v.y; az += v.z; aw += v.w;
            }
            rsum += (((q0.x + q0.y) + (q0.z + q0.w)) + ((q1.x + q1.y) + (q1.z + q1.w)))
                  + (((q2.x + q2.y) + (q2.z + q2.w)) + ((q3.x + q3.y) + (q3.z + q3.w)));
        }

        // Hall writes at end of each chunk
        if (s == 3) {
            float4 rr; rr.x = ax; rr.y = ay; rr.z = az; rr.w = aw;
            *(float4*)(g_Hall + (size_t)(b0 + bl) * NCOLS + (cg * 2) * 32 + c4 * 4) = rr;
            ax = ay = az = aw = 0.f;
        }
        if (s == 7) {
            float4 rr; rr.x = ax; rr.y = ay; rr.z = az; rr.w = aw;
            *(float4*)(g_Hall + (size_t)(b0 + bl) * NCOLS + (cg * 2 + 1) * 32 + c4 * 4) = rr;
        }

        // conn row reduction for this subtile
        if (doConn) {
#pragma unroll
            for (int o = 16; o; o >>= 1) rsum += __shfl_xor_sync(0xffffffffu, rsum, o);
            if ((tid & 31) == 0) ws[tid >> 5] = rsum;
        }
        __syncthreads();   // protects ws AND tileS before next subtile load
        if (doConn && tid == 0) {
            float t = 0.f;
#pragma unroll
            for (int i = 0; i < 16; i++) t += ws[i];
            g_NumConn[row] = t;
        }
    }
}

// ---------------------------------------------------------------------------
// Finalize: heads, entropies, 3-layer correctness MLP.  (round-2 version)
// ---------------------------------------------------------------------------
__device__ __forceinline__ float softplusf_(float x) {
    return (x > 20.f) ? x : log1pf(expf(x));
}
__device__ __forceinline__ float sigmoidf_(float x) {
    return 1.f / (1.f + expf(-x));
}

#define F_H1S   0        // 4096
#define F_CW2T  4096     // 8192
#define F_BIAS  12288    // 768
#define F_CB1   13056    // 256
#define F_WIN   13312    // 3072
#define F_REDA  16384    // 128
#define F_PACC  16512    // 2048
#define F_RED2  18560    // 64
#define F_TOT   18624

__global__ void finalize_kernel(const int* __restrict__ gate_types,
                                const float* __restrict__ inputs,
                                const float* __restrict__ outputs,
                                const float* __restrict__ pb1, const float* __restrict__ pw2, const float* __restrict__ pb2,
                                const float* __restrict__ db1, const float* __restrict__ dw2, const float* __restrict__ db2,
                                const float* __restrict__ nb1, const float* __restrict__ nw2, const float* __restrict__ nb2,
                                const float* __restrict__ cw1, const float* __restrict__ cb1,
                                const float* __restrict__ cw2, const float* __restrict__ cb2,
                                const float* __restrict__ cw3, const float* __restrict__ cb3,
                                float* __restrict__ out) {
    extern __shared__ float sD[];
    float* h1s   = sD + F_H1S;
    float* cw2t  = sD + F_CW2T;
    float* biasS = sD + F_BIAS;
    float* cb1S  = sD + F_CB1;
    float* winS  = sD + F_WIN;
    float* redA  = sD + F_REDA;
    float* pacc  = sD + F_PACC;
    float* red2  = sD + F_RED2;

    const int tid  = threadIdx.x;
    const int lane = tid & 31, warp = tid >> 5;
    const int gb   = blockIdx.x * 16;

    if (tid < 128) {
        biasS[tid]       = pb1[tid];
        biasS[128 + tid] = db1[tid];
        biasS[256 + tid] = nb1[tid];
        biasS[384 + tid] = pw2[tid];
        biasS[512 + tid] = dw2[tid];
        biasS[640 + tid] = nw2[tid];
    }
    cb1S[tid] = cb1[tid];
    const float* winsrc = cw1 + 8192 * 256;
    for (int i = tid; i < 3072; i += 256) winS[i] = winsrc[i];
    __syncthreads();

    for (int q = 0; q < 2; q++) {
        const int bl = warp * 2 + q;
        const int b  = gb + bl;
        const float* H = g_Hall + (size_t)b * NCOLS;

        float vp = 0.f, vd = 0.f, vn = 0.f;
#pragma unroll
        for (int k = 0; k < 4; k++) {
            int c = lane + 32 * k;
            float hp = fmaxf(H[c]       + biasS[c],       0.f);
            float hd = fmaxf(H[128 + c] + biasS[128 + c], 0.f);
            float hn = fmaxf(H[256 + c] + biasS[256 + c], 0.f);
            vp += hp * biasS[384 + c];
            vd += hd * biasS[512 + c];
            vn += hn * biasS[640 + c];
        }

        const int4* tq = (const int4*)(gate_types + (size_t)b * Gn);
        int4 ta = tq[lane * 2], tb = tq[lane * 2 + 1];
        float c0, c1, c2, c3;
        {
            int k0 = (ta.x == 0) + (ta.y == 0) + (ta.z == 0) + (ta.w == 0)
                   + (tb.x == 0) + (tb.y == 0) + (tb.z == 0) + (tb.w == 0);
            int k1 = (ta.x == 1) + (ta.y == 1) + (ta.z == 1) + (ta.w == 1)
                   + (tb.x == 1) + (tb.y == 1) + (tb.z == 1) + (tb.w == 1);
            int k2 = (ta.x == 2) + (ta.y == 2) + (ta.z == 2) + (ta.w == 2)
                   + (tb.x == 2) + (tb.y == 2) + (tb.z == 2) + (tb.w == 2);
            int k3 = (ta.x == 3) + (ta.y == 3) + (ta.z == 3) + (ta.w == 3)
                   + (tb.x == 3) + (tb.y == 3) + (tb.z == 3) + (tb.w == 3);
            c0 = (float)k0; c1 = (float)k1; c2 = (float)k2; c3 = (float)k3;
        }

        float xv = 0.f;
        if (lane < 8)        xv = inputs[b * 8 + lane];
        else if (lane < 12)  xv = outputs[b * 4 + lane - 8];

#pragma unroll
        for (int k = 0; k < 8; k++) {
            int c2i = lane + 32 * k;
            float ha = H[384 + c2i] + cb1S[c2i];
#pragma unroll
            for (int i = 0; i < 12; i++) {
                float x = __shfl_sync(0xffffffffu, xv, i);
                ha += x * winS[i * 256 + c2i];
            }
            h1s[bl * 256 + c2i] = fmaxf(ha, 0.f);
        }

#pragma unroll
        for (int o = 16; o; o >>= 1) {
            vp += __shfl_xor_sync(0xffffffffu, vp, o);
            vd += __shfl_xor_sync(0xffffffffu, vd, o);
            vn += __shfl_xor_sync(0xffffffffu, vn, o);
            c0 += __shfl_xor_sync(0xffffffffu, c0, o);
            c1 += __shfl_xor_sync(0xffffffffu, c1, o);
            c2 += __shfl_xor_sync(0xffffffffu, c2, o);
            c3 += __shfl_xor_sync(0xffffffffu, c3, o);
        }
        if (lane == 0) {
            float* rr = redA + bl * 8;
            rr[0] = vp; rr[1] = vd; rr[2] = vn;
            rr[3] = c0; rr[4] = c1; rr[5] = c2; rr[6] = c3;
        }
    }
    __syncthreads();

    if (tid < 16) {
        const int b = gb + tid;
        float* rr = redA + tid * 8;
        float nc = g_NumConn[b];
        float energy = softplusf_(rr[0] + pb2[0]) + 0.05f * nc;
        float delay  = softplusf_(rr[1] + db2[0]);
        float stab   = sigmoidf_(rr[2] + nb2[0]) * 0.36787944117144233f;
        float ent = 0.f;
#pragma unroll
        for (int i = 0; i < 4; i++) {
            float p = rr[3 + i] * (1.f / 256.f);
            if (p > 0.f) ent -= p * log2f(p);
        }
        float dens = nc * (1.f / 65536.f);
        if (dens > 0.f && dens < 1.f) {
            float d = fminf(fmaxf(dens, 1e-12f), 1.f - 1e-12f);
            ent += -d * log2f(d) - (1.f - d) * log2f(1.f - d);
        }
        out[b]            = energy;
        out[4096 + b]     = ent;
        out[2 * 4096 + b] = stab;
        out[4 * 4096 + b] = delay;
    }

    const int col = tid & 127;
    const int sub = tid >> 7;
    float acc[16];
#pragma unroll
    for (int i = 0; i < 16; i++) acc[i] = 0.f;

    for (int jc = 0; jc < 4; jc++) {
        __syncthreads();
        const float4* src = (const float4*)(cw2 + jc * 64 * 128);
        float4* dst = (float4*)cw2t;
        for (int i = tid; i < 2048; i += 256) dst[i] = src[i];
        __syncthreads();

        const int jbase = sub * 32;
#pragma unroll
        for (int jj0 = 0; jj0 < 32; jj0 += 4) {
            float w0 = cw2t[(jbase + jj0 + 0) * 128 + col];
            float w1 = cw2t[(jbase + jj0 + 1) * 128 + col];
            float w2v = cw2t[(jbase + jj0 + 2) * 128 + col];
            float w3v = cw2t[(jbase + jj0 + 3) * 128 + col];
#pragma unroll
            for (int blx = 0; blx < 16; blx++) {
                float4 h = *(const float4*)&h1s[blx * 256 + jc * 64 + jbase + jj0];
                acc[blx] += h.x * w0 + h.y * w1 + h.z * w2v + h.w * w3v;
            }
        }
    }
    __syncthreads();
    if (sub == 1) {
#pragma unroll
        for (int blx = 0; blx < 16; blx++) pacc[blx * 128 + col] = acc[blx];
    }
    __syncthreads();
    if (sub == 0) {
        const float cb2j = cb2[col], w3 = cw3[col];
#pragma unroll
        for (int blx = 0; blx < 16; blx++) {
            float a = acc[blx] + pacc[blx * 128 + col];
            float h2 = fmaxf(a + cb2j, 0.f);
            float v  = h2 * w3;
#pragma unroll
            for (int o = 16; o; o >>= 1) v += __shfl_xor_sync(0xffffffffu, v, o);
            if (lane == 0) red2[blx * 4 + warp] = v;
        }
    }
    __syncthreads();
    if (tid < 16) {
        float s = red2[tid * 4] + red2[tid * 4 + 1] + red2[tid * 4 + 2] + red2[tid * 4 + 3];
        out[3 * 4096 + gb + tid] = sigmoidf_(s + cb3[0]);
    }
}

// ---------------------------------------------------------------------------
extern "C" void kernel_launch(void* const* d_in, const int* in_sizes, int n_in,
                              void* d_out, int out_size) {
    (void)in_sizes; (void)n_in; (void)out_size;
    const int*   gate_types  = (const int*)  d_in[0];
    const float* connections = (const float*)d_in[1];
    const float* inputs      = (const float*)d_in[2];
    const float* outputs     = (const float*)d_in[3];
    const float* emb         = (const float*)d_in[4];
    const float* pw1 = (const float*)d_in[5];
    const float* pb1 = (const float*)d_in[6];
    const float* pw2 = (const float*)d_in[7];
    const float* pb2 = (const float*)d_in[8];
    const float* dw1 = (const float*)d_in[9];
    const float* db1 = (const float*)d_in[10];
    const float* dw2 = (const float*)d_in[11];
    const float* db2 = (const float*)d_in[12];
    const float* nw1 = (const float*)d_in[13];
    const float* nb1 = (const float*)d_in[14];
    const float* nw2 = (const float*)d_in[15];
    const float* nb2 = (const float*)d_in[16];
    const float* cw1 = (const float*)d_in[17];
    const float* cb1 = (const float*)d_in[18];
    const float* cw2 = (const float*)d_in[19];
    const float* cb2 = (const float*)d_in[20];
    const float* cw3 = (const float*)d_in[21];
    const float* cb3 = (const float*)d_in[22];
    float* out = (float*)d_out;

    const int smemF = 16384 * 4 + 1024 * 4 + 64;   // 69696 B
    const int smemD = F_TOT * 4;                   // 74496 B
    cudaFuncSetAttribute(fused_main,      cudaFuncAttributeMaxDynamicSharedMemorySize, smemF);
    cudaFuncSetAttribute(finalize_kernel, cudaFuncAttributeMaxDynamicSharedMemorySize, smemD);

    precompute_P<<<256, 640>>>(emb, pw1, dw1, nw1, cw1);
    build_P2<<<128, 640>>>();
    fused_main<<<640, 512, smemF>>>(connections, gate_types);
    finalize_kernel<<<256, 256, smemD>>>(gate_types, inputs, outputs,
                                         pb1, pw2, pb2, db1, dw2, db2,
                                         nb1, nw2, nb2, cw1, cb1,
                                         cw2, cb2, cw3, cb3, out);
}